// round 11
// baseline (speedup 1.0000x reference)
#include <cuda_runtime.h>
#include <cuda_fp16.h>
#include <cstdint>
#include <cstddef>

typedef __half f16;

#define T_ 256
#define B_ 64
#define D_ 512
#define H_ 1024
#define G_ 4096
#define TB_ (T_ * B_)
#define OUTS_ (TB_ * H_)
#define NB_ 128          // persistent grid size

// ---------------- device scratch ----------------
__device__ f16   g_Xp  [(size_t)TB_ * D_];       // input fp16, stride 512
__device__ f16   g_Wi0p[(size_t)G_  * D_];       // fp16 weights (gate-row permuted)
__device__ f16   g_Wh0p[(size_t)G_  * H_];
__device__ f16   g_Wi1p[(size_t)G_  * H_];
__device__ f16   g_Wh1p[(size_t)G_  * H_];
__device__ float g_b0[G_], g_b1[G_];
__device__ float g_G0[(size_t)TB_ * G_];
__device__ float g_c0s[2 * B_ * H_];
__device__ f16   g_h0p[2][B_ * H_];              // h0 ping-pong
__device__ f16   g_h1p[2][B_ * H_];              // h1 ping-pong
__device__ unsigned g_bar_grp[8];    // zero-init
__device__ unsigned g_bar_root;      // zero-init
__device__ unsigned g_bar_gen;       // zero-init, monotonic

// ---------------- helpers ----------------
__device__ __forceinline__ void cp_async16(void* sdst, const void* gsrc) {
    uint32_t s = (uint32_t)__cvta_generic_to_shared(sdst);
    asm volatile("cp.async.cg.shared.global [%0], [%1], 16;\n" :: "r"(s), "l"(gsrc));
}
__device__ __forceinline__ void cp_commit() { asm volatile("cp.async.commit_group;\n"); }
template <int N> __device__ __forceinline__ void cp_wait() {
    asm volatile("cp.async.wait_group %0;\n" :: "n"(N));
}
__device__ __forceinline__ unsigned ld_acq(const unsigned* p) {
    unsigned v; asm volatile("ld.acquire.gpu.u32 %0, [%1];" : "=r"(v) : "l"(p)); return v;
}
__device__ __forceinline__ void mma16816(float* d,
    uint32_t a0, uint32_t a1, uint32_t a2, uint32_t a3, uint32_t b0, uint32_t b1)
{
    asm volatile(
        "mma.sync.aligned.m16n8k16.row.col.f32.f16.f16.f32 "
        "{%0,%1,%2,%3},{%4,%5,%6,%7},{%8,%9},{%0,%1,%2,%3};\n"
        : "+f"(d[0]), "+f"(d[1]), "+f"(d[2]), "+f"(d[3])
        : "r"(a0), "r"(a1), "r"(a2), "r"(a3), "r"(b0), "r"(b1));
}
__device__ __forceinline__ void ldsm4(uint32_t& a, uint32_t& b, uint32_t& c, uint32_t& d,
                                      uint32_t addr)
{
    asm volatile("ldmatrix.sync.aligned.m8n8.x4.shared.b16 {%0,%1,%2,%3}, [%4];"
        : "=r"(a), "=r"(b), "=r"(c), "=r"(d) : "r"(addr));
}
__device__ __forceinline__ float sigmoidf_(float z) { return 1.f / (1.f + __expf(-z)); }

// ---------------- packing ----------------
__global__ void pack_w_kernel(const float* __restrict__ src, int which, int K)
{
    f16* dst = (which == 0) ? g_Wi0p : (which == 1) ? g_Wh0p :
               (which == 2) ? g_Wi1p : g_Wh1p;
    int K4 = K >> 2;
    int total = G_ * K4;
    for (int id = blockIdx.x * blockDim.x + threadIdx.x; id < total;
         id += gridDim.x * blockDim.x) {
        int r = id / K4, k4 = (id - r * K4) * 4;
        int sr = (r & 3) * H_ + (r >> 2);
        float4 v = *(const float4*)&src[(size_t)sr * K + k4];
        __half2 a = {__float2half_rn(v.x), __float2half_rn(v.y)};
        __half2 b = {__float2half_rn(v.z), __float2half_rn(v.w)};
        *(uint2*)&dst[(size_t)r * K + k4] = make_uint2(*(uint32_t*)&a, *(uint32_t*)&b);
    }
}

__global__ void pack_x_kernel(const float* __restrict__ src)
{
    int total = TB_ * (D_ >> 2);
    for (int id = blockIdx.x * blockDim.x + threadIdx.x; id < total;
         id += gridDim.x * blockDim.x) {
        int r = id / (D_ >> 2), k4 = (id - r * (D_ >> 2)) * 4;
        float4 v = *(const float4*)&src[(size_t)r * D_ + k4];
        __half2 a = {__float2half_rn(v.x), __float2half_rn(v.y)};
        __half2 b = {__float2half_rn(v.z), __float2half_rn(v.w)};
        *(uint2*)&g_Xp[(size_t)r * D_ + k4] = make_uint2(*(uint32_t*)&a, *(uint32_t*)&b);
    }
}

__global__ void bias_kernel(const float* __restrict__ bi0, const float* __restrict__ bh0,
                            const float* __restrict__ bi1, const float* __restrict__ bh1)
{
    int r = blockIdx.x * blockDim.x + threadIdx.x;
    if (r < G_) {
        int sr = (r & 3) * H_ + (r >> 2);
        g_b0[r] = bi0[sr] + bh0[sr];
        g_b1[r] = bi1[sr] + bh1[sr];
    }
}

__global__ void init_state_kernel(const float* __restrict__ h0, const float* __restrict__ c0)
{
    int id = blockIdx.x * blockDim.x + threadIdx.x;
    if (id < 2 * B_ * H_) {
        int l = id / (B_ * H_);
        int b = (id / H_) % B_;
        int j = id % H_;
        float hv = h0[(b * 2 + l) * H_ + j];
        g_c0s[id] = c0[(b * 2 + l) * H_ + j];
        f16 hh = __float2half_rn(hv);
        if (l == 0) g_h0p[0][b * H_ + j] = hh;
        else        g_h1p[0][b * H_ + j] = hh;
    }
}

// ---------------- G0 GEMM: g_G0 = Xp @ Wi0p^T + b0 ----------------
#define GAS 72
__global__ __launch_bounds__(256) void gemm_kernel()
{
    extern __shared__ f16 sm[];
    const int AS = 128 * GAS;
    f16* sA = sm;
    f16* sB = sm + 3 * AS;
    uint32_t sA_u = (uint32_t)__cvta_generic_to_shared(sA);
    uint32_t sB_u = (uint32_t)__cvta_generic_to_shared(sB);

    const f16 *A = g_Xp, *B = g_Wi0p;
    const float* bias = g_b0;
    float* outp = g_G0;
    const int K = 512;

    int tid = threadIdx.x, w = tid >> 5, lane = tid & 31, g = lane >> 2, t4 = lane & 3;
    int wm = w & 1, wn = w >> 1;
    int m0 = blockIdx.y * 128, n0 = blockIdx.x * 128;
    const int NC = K / 64;

    int lr = lane & 15;
    int lcA = (lane >> 4) * 8;
    uint32_t aBase[4], bBase[2];
#pragma unroll
    for (int mt = 0; mt < 4; mt++)
        aBase[mt] = (uint32_t)(((wm * 64 + mt * 16 + lr) * GAS + lcA) * 2);
#pragma unroll
    for (int p = 0; p < 2; p++)
        bBase[p] = (uint32_t)(((wn * 32 + p * 16 + (lane & 7) + ((lane >> 4) & 1) * 8) * GAS
                               + ((lane >> 3) & 1) * 8) * 2);

    float acc[4][4][4];
#pragma unroll
    for (int a = 0; a < 4; a++)
#pragma unroll
        for (int b = 0; b < 4; b++)
#pragma unroll
            for (int c = 0; c < 4; c++) acc[a][b][c] = 0.f;

    auto issue = [&](int c) {
        int k0 = c * 64;
        int st = c % 3;
#pragma unroll
        for (int v = 0; v < 4; v++) {
            int idx = tid + v * 256;
            int r = idx >> 3, s = idx & 7;
            cp_async16(&sA[st * AS + r * GAS + s * 8], &A[(size_t)(m0 + r) * K + k0 + s * 8]);
        }
#pragma unroll
        for (int v = 0; v < 4; v++) {
            int idx = tid + v * 256;
            int r = idx >> 3, s = idx & 7;
            cp_async16(&sB[st * AS + r * GAS + s * 8], &B[(size_t)(n0 + r) * K + k0 + s * 8]);
        }
        cp_commit();
    };

    issue(0); issue(1);
    for (int c = 0; c < NC; c++) {
        if (c + 1 < NC) cp_wait<1>(); else cp_wait<0>();
        __syncthreads();
        if (c + 2 < NC) issue(c + 2);
        uint32_t stA = sA_u + (uint32_t)((c % 3) * AS * 2);
        uint32_t stB = sB_u + (uint32_t)((c % 3) * AS * 2);
#pragma unroll
        for (int kk = 0; kk < 4; kk++) {
            uint32_t kbb = (uint32_t)(kk * 32);
            uint32_t Aa[4][4], Bh[4][2];
#pragma unroll
            for (int mt = 0; mt < 4; mt++)
                ldsm4(Aa[mt][0], Aa[mt][1], Aa[mt][2], Aa[mt][3], stA + aBase[mt] + kbb);
#pragma unroll
            for (int p = 0; p < 2; p++)
                ldsm4(Bh[2 * p][0], Bh[2 * p][1], Bh[2 * p + 1][0], Bh[2 * p + 1][1],
                      stB + bBase[p] + kbb);
#pragma unroll
            for (int mt = 0; mt < 4; mt++)
#pragma unroll
                for (int nt = 0; nt < 4; nt++)
                    mma16816(acc[mt][nt], Aa[mt][0], Aa[mt][1], Aa[mt][2], Aa[mt][3], Bh[nt][0], Bh[nt][1]);
        }
    }

#pragma unroll
    for (int mt = 0; mt < 4; mt++)
#pragma unroll
        for (int nt = 0; nt < 4; nt++) {
            int row = m0 + wm * 64 + mt * 16 + g;
            int col = n0 + wn * 32 + nt * 8 + 2 * t4;
            float ba = bias[col], bb = bias[col + 1];
            *(float2*)&outp[(size_t)row * G_ + col] =
                make_float2(acc[mt][nt][0] + ba, acc[mt][nt][1] + bb);
            *(float2*)&outp[(size_t)(row + 8) * G_ + col] =
                make_float2(acc[mt][nt][2] + ba, acc[mt][nt][3] + bb);
        }
}

// ---------------- merged persistent wavefront kernel (single tri-GEMM mainloop) ----------------
// 128 CTAs x 256 threads, 257 super-steps. Super-step s:
//   layer0 step t=s   (s<256): z0 = G0[s] + keep0*(h0_{s-1} @ Wh0)
//   layer1 step t=s-1 (s>=1):  z1 = b1 + h0_{s-1}@Wi1 + keep1*(h1_{s-2} @ Wh1)
// ONE mainloop: A-ring stage = [A0 64 rows | A1 64 rows] x 64 cols; Wi1 streamed in B-ring;
// Wh0+Wh1 resident. 16 chunks, 3-stage ring, distance-2 issue.
#define WSTR 1032
#define ASTR2 72
#define ASTG2 (128 * ASTR2)     // elems per A stage
#define BSTG2 (32 * ASTR2)      // elems per B stage
#define ZBANK (64 * 36)

__global__ __launch_bounds__(256, 1) void merged_kernel(const int* __restrict__ reset,
                                                        float* __restrict__ out)
{
    extern __shared__ f16 smem[];
    f16* sW0 = smem;                       // Wh0 slice: 32 x WSTR
    f16* sW1 = smem + 32 * WSTR;           // Wh1 slice: 32 x WSTR
    f16* sA  = smem + 64 * WSTR;           // 3 x ASTG2
    f16* sB  = sA + 3 * ASTG2;             // 3 x BSTG2 (Wi1 ring)
    float* zs = (float*)(sB + 3 * BSTG2);  // 2 banks x 64 x 36 (reused layer0 then layer1)
    uint32_t sW0_u = (uint32_t)__cvta_generic_to_shared(sW0);
    uint32_t sW1_u = (uint32_t)__cvta_generic_to_shared(sW1);
    uint32_t sA_u  = (uint32_t)__cvta_generic_to_shared(sA);
    uint32_t sB_u  = (uint32_t)__cvta_generic_to_shared(sB);

    int tid = threadIdx.x, w = tid >> 5, lane = tid & 31, g = lane >> 2, t4 = lane & 3;
    int wk = w & 1, wn = (w >> 1) & 1, wm = w >> 2;
    int n0 = blockIdx.x * 32;
    unsigned gen0 = ld_acq(&g_bar_gen);

    // resident W slices
    for (int i = tid; i < 32 * 128; i += 256) {
        int r = i >> 7, sseg = i & 127;
        *(uint4*)&sW0[r * WSTR + sseg * 8] = *(const uint4*)&g_Wh0p[(size_t)(n0 + r) * H_ + sseg * 8];
        *(uint4*)&sW1[r * WSTR + sseg * 8] = *(const uint4*)&g_Wh1p[(size_t)(n0 + r) * H_ + sseg * 8];
    }

    // ldmatrix bases
    int lr = lane & 15;
    int lcA = (lane >> 4) * 8;
    uint32_t aBase[2];
    aBase[0] = (uint32_t)(((wm * 32 + 0 + lr) * ASTR2 + lcA) * 2);
    aBase[1] = (uint32_t)(((wm * 32 + 16 + lr) * ASTR2 + lcA) * 2);
    const uint32_t A1OFF = (uint32_t)(64 * ASTR2 * 2);   // A1 rows start
    uint32_t wBase[2], biBase[2];
#pragma unroll
    for (int nt = 0; nt < 2; nt++) {
        wBase[nt]  = (uint32_t)(((wn * 16 + nt * 8 + (lane & 7)) * WSTR
                                 + ((lane >> 3) & 1) * 8 + ((lane >> 4) & 1) * 16) * 2);
        biBase[nt] = (uint32_t)(((wn * 16 + nt * 8 + (lane & 7)) * ASTR2
                                 + ((lane >> 3) & 1) * 8 + ((lane >> 4) & 1) * 16) * 2);
    }
    const uint32_t kpb = (uint32_t)(wk * 64);   // this warp's k32 block (bytes) within a 64-col chunk

    int bb = tid >> 3, jl = tid & 7, j = blockIdx.x * 8 + jl;
    int bb2 = (tid + 256) >> 3;
    int wrow[4] = { wm * 32 + g, wm * 32 + 8 + g, wm * 32 + 16 + g, wm * 32 + 24 + g };

    float c0r[2], c1r[2];
    c0r[0] = g_c0s[(0 * B_ + bb) * H_ + j];
    c0r[1] = g_c0s[(0 * B_ + bb2) * H_ + j];
    c1r[0] = g_c0s[(1 * B_ + bb) * H_ + j];
    c1r[1] = g_c0s[(1 * B_ + bb2) * H_ + j];

    float4 b1v = *(const float4*)&g_b1[n0 + 4 * jl];

    float4 gp[2]; float rst0[2], rst1[2], kw[4];
    gp[0] = *(const float4*)&g_G0[(size_t)bb * G_ + n0 + 4 * jl];
    gp[1] = *(const float4*)&g_G0[(size_t)bb2 * G_ + n0 + 4 * jl];
    rst0[0] = (float)reset[bb];
    rst0[1] = (float)reset[bb2];
    rst1[0] = rst1[1] = 0.f;
    kw[0] = kw[1] = kw[2] = kw[3] = 1.f;
    __syncthreads();

    for (int s = 0; s <= T_; s++) {
        const f16* A0 = g_h0p[s & 1];          // h0_{s-1}
        const f16* A1 = g_h1p[(s + 1) & 1];    // h1_{s-2}

        float acc0[2][2][4], accWi[2][2][4], accWh[2][2][4];
#pragma unroll
        for (int a = 0; a < 2; a++)
#pragma unroll
            for (int b = 0; b < 2; b++)
#pragma unroll
                for (int c = 0; c < 4; c++) {
                    acc0[a][b][c] = 0.f; accWi[a][b][c] = 0.f; accWh[a][b][c] = 0.f;
                }

        // ---- single fused mainloop: {A0,A1} vs {Wh0 res, Wi1 ring, Wh1 res} ----
        auto issueF = [&](int c) {
            int k0 = c * 64, st = c % 3;
#pragma unroll
            for (int v = 0; v < 4; v++) {           // 128 rows (A0|A1) x 8 segs
                int idx = tid + v * 256;
                int r = idx >> 3, sseg = idx & 7;
                const f16* src = (r < 64) ? &A0[(size_t)r * H_ + k0 + sseg * 8]
                                          : &A1[(size_t)(r - 64) * H_ + k0 + sseg * 8];
                cp_async16(&sA[st * ASTG2 + r * ASTR2 + sseg * 8], src);
            }
            {                                        // Wi1: 32 rows x 8 segs
                int r = tid >> 3, sseg = tid & 7;
                cp_async16(&sB[st * BSTG2 + r * ASTR2 + sseg * 8],
                           &g_Wi1p[(size_t)(n0 + r) * H_ + k0 + sseg * 8]);
            }
            cp_commit();
        };

        issueF(0); issueF(1);
        for (int c = 0; c < 16; c++) {
            if (c + 1 < 16) cp_wait<1>(); else cp_wait<0>();
            __syncthreads();
            if (c + 2 < 16) issueF(c + 2);
            uint32_t stA = sA_u + (uint32_t)((c % 3) * ASTG2 * 2);
            uint32_t stB = sB_u + (uint32_t)((c % 3) * BSTG2 * 2);
            uint32_t wOffC = (uint32_t)(c * 128);   // c*64 cols * 2B

            uint32_t Bq0[2][4], BqW[2][4], Bq1[2][4];
#pragma unroll
            for (int nt = 0; nt < 2; nt++) {
                ldsm4(Bq0[nt][0], Bq0[nt][1], Bq0[nt][2], Bq0[nt][3],
                      sW0_u + wBase[nt] + wOffC + kpb);
                ldsm4(Bq1[nt][0], Bq1[nt][1], Bq1[nt][2], Bq1[nt][3],
                      sW1_u + wBase[nt] + wOffC + kpb);
                ldsm4(BqW[nt][0], BqW[nt][1], BqW[nt][2], BqW[nt][3],
                      stB + biBase[nt] + kpb);
            }
#pragma unroll
            for (int h = 0; h < 2; h++) {
                uint32_t kbb = kpb + (uint32_t)(h * 32);
                uint32_t A0f[2][4], A1f[2][4];
#pragma unroll
                for (int mt = 0; mt < 2; mt++) {
                    ldsm4(A0f[mt][0], A0f[mt][1], A0f[mt][2], A0f[mt][3], stA + aBase[mt] + kbb);
                    ldsm4(A1f[mt][0], A1f[mt][1], A1f[mt][2], A1f[mt][3], stA + aBase[mt] + A1OFF + kbb);
                }
#pragma unroll
                for (int mt = 0; mt < 2; mt++)
#pragma unroll
                    for (int nt = 0; nt < 2; nt++) {
                        mma16816(acc0[mt][nt],  A0f[mt][0], A0f[mt][1], A0f[mt][2], A0f[mt][3],
                                 Bq0[nt][h * 2], Bq0[nt][h * 2 + 1]);
                        mma16816(accWi[mt][nt], A0f[mt][0], A0f[mt][1], A0f[mt][2], A0f[mt][3],
                                 BqW[nt][h * 2], BqW[nt][h * 2 + 1]);
                        mma16816(accWh[mt][nt], A1f[mt][0], A1f[mt][1], A1f[mt][2], A1f[mt][3],
                                 Bq1[nt][h * 2], Bq1[nt][h * 2 + 1]);
                    }
            }
        }

        // ---- layer0 partials -> zs ----
        {
            float* zb = zs + wk * ZBANK;
#pragma unroll
            for (int mt = 0; mt < 2; mt++)
#pragma unroll
                for (int nt = 0; nt < 2; nt++) {
                    int r0 = wm * 32 + mt * 16 + g;
                    int c0 = wn * 16 + nt * 8 + 2 * t4;
                    zb[r0 * 36 + c0]     = acc0[mt][nt][0];
                    zb[r0 * 36 + c0 + 1] = acc0[mt][nt][1];
                    zb[(r0 + 8) * 36 + c0]     = acc0[mt][nt][2];
                    zb[(r0 + 8) * 36 + c0 + 1] = acc0[mt][nt][3];
                }
        }
        __syncthreads();

        // ---- tail0: layer0 activation, store h0_s ----
        if (s < T_) {
#pragma unroll
            for (int it = 0; it < 2; it++) {
                int b = it ? bb2 : bb;
                float keep = 1.0f - rst0[it];
                int zi_i = b * 36 + 4 * jl;
                float zi = gp[it].x + keep * (zs[zi_i + 0] + zs[ZBANK + zi_i + 0]);
                float zf = gp[it].y + keep * (zs[zi_i + 1] + zs[ZBANK + zi_i + 1]);
                float zg = gp[it].z + keep * (zs[zi_i + 2] + zs[ZBANK + zi_i + 2]);
                float zo = gp[it].w + keep * (zs[zi_i + 3] + zs[ZBANK + zi_i + 3]);
                float cn = sigmoidf_(zf) * keep * c0r[it] + sigmoidf_(zi) * tanhf(zg);
                float hn = sigmoidf_(zo) * tanhf(cn);
                c0r[it] = cn;
                g_h0p[(s + 1) & 1][b * H_ + j] = __float2half_rn(hn);
                if (s == T_ - 1) {
                    out[OUTS_ + (b * 2 + 0) * H_ + j] = hn;
                    out[OUTS_ + 2 * B_ * H_ + (b * 2 + 0) * H_ + j] = cn;
                }
            }
        }
        __syncthreads();   // tail0 zs reads complete before overwrite

        float hn_s[2], cn_s[2];
        if (s >= 1) {
            // ---- layer1 partials: zs = kw*accWh + accWi (writer-side keep; kw in {0,1}) ----
            {
                float* zb = zs + wk * ZBANK;
#pragma unroll
                for (int mt = 0; mt < 2; mt++)
#pragma unroll
                    for (int nt = 0; nt < 2; nt++) {
                        int r0 = wm * 32 + mt * 16 + g;
                        int c0 = wn * 16 + nt * 8 + 2 * t4;
                        float k0f = kw[mt * 2 + 0], k1f = kw[mt * 2 + 1];
                        zb[r0 * 36 + c0]     = k0f * accWh[mt][nt][0] + accWi[mt][nt][0];
                        zb[r0 * 36 + c0 + 1] = k0f * accWh[mt][nt][1] + accWi[mt][nt][1];
                        zb[(r0 + 8) * 36 + c0]     = k1f * accWh[mt][nt][2] + accWi[mt][nt][2];
                        zb[(r0 + 8) * 36 + c0 + 1] = k1f * accWh[mt][nt][3] + accWi[mt][nt][3];
                    }
            }
            __syncthreads();

            // ---- tail1: layer1 activation, store h1_{s-1} ----
#pragma unroll
            for (int it = 0; it < 2; it++) {
                int b = it ? bb2 : bb;
                float keep = 1.0f - rst1[it];
                int zi_i = b * 36 + 4 * jl;
                float zi = b1v.x + (zs[zi_i + 0] + zs[ZBANK + zi_i + 0]);
                float zf = b1v.y + (zs[zi_i + 1] + zs[ZBANK + zi_i + 1]);
                float zg = b1v.z + (zs[zi_i + 2] + zs[ZBANK + zi_i + 2]);
                float zo = b1v.w + (zs[zi_i + 3] + zs[ZBANK + zi_i + 3]);
                float cn = sigmoidf_(zf) * keep * c1r[it] + sigmoidf_(zi) * tanhf(zg);
                float hn = sigmoidf_(zo) * tanhf(cn);
                c1r[it] = cn; cn_s[it] = cn; hn_s[it] = hn;
                g_h1p[s & 1][b * H_ + j] = __float2half_rn(hn);
                if (s == T_) {
                    out[OUTS_ + (b * 2 + 1) * H_ + j] = hn;
                    out[OUTS_ + 2 * B_ * H_ + (b * 2 + 1) * H_ + j] = cn;
                }
            }
        }

        // ---- barrier arrive ----
        __syncthreads();
        if (tid == 0) {
            __threadfence();
            unsigned grp = (unsigned)blockIdx.x >> 4;
            if (atomicAdd(&g_bar_grp[grp], 1u) == 15u) {
                g_bar_grp[grp] = 0u;
                if (atomicAdd(&g_bar_root, 1u) == 7u) {
                    g_bar_root = 0u;
                    __threadfence();
                    g_bar_gen = gen0 + s + 1;
                }
            }
        }

        // ---- overlap: output stores + prefetch for super-step s+1 ----
        if (s >= 1) {
            int t1 = s - 1;
#pragma unroll
            for (int it = 0; it < 2; it++) {
                int b = it ? bb2 : bb;
                out[(size_t)t1 * B_ * H_ + b * H_ + j] = hn_s[it];
            }
        }
        if (s + 1 <= T_) {
            rst1[0] = rst0[0]; rst1[1] = rst0[1];
            if (s + 1 < T_) {
                gp[0] = *(const float4*)&g_G0[((size_t)(s + 1) * B_ + bb) * G_ + n0 + 4 * jl];
                gp[1] = *(const float4*)&g_G0[((size_t)(s + 1) * B_ + bb2) * G_ + n0 + 4 * jl];
                rst0[0] = (float)reset[(s + 1) * B_ + bb];
                rst0[1] = (float)reset[(s + 1) * B_ + bb2];
            }
#pragma unroll
            for (int i = 0; i < 4; i++)
                kw[i] = 1.0f - (float)reset[s * B_ + wrow[i]];
        }

        if (tid == 0) {
            while (ld_acq(&g_bar_gen) < gen0 + s + 1) { }
        }
        __syncthreads();
    }
}

// ---------------- launch ----------------
extern "C" void kernel_launch(void* const* d_in, const int* in_sizes, int n_in,
                              void* d_out, int out_size)
{
    (void)in_sizes; (void)n_in; (void)out_size;
    const float* input = (const float*)d_in[0];
    const int*   reset = (const int*)d_in[1];
    const float* h0    = (const float*)d_in[2];
    const float* c0    = (const float*)d_in[3];
    const float* Wi0   = (const float*)d_in[4];
    const float* Wh0   = (const float*)d_in[5];
    const float* bi0   = (const float*)d_in[6];
    const float* bh0   = (const float*)d_in[7];
    const float* Wi1   = (const float*)d_in[8];
    const float* Wh1   = (const float*)d_in[9];
    const float* bi1   = (const float*)d_in[10];
    const float* bh1   = (const float*)d_in[11];
    float* out = (float*)d_out;

    const int GEMM_SMEM   = 6 * 128 * GAS * 2;                                       // 110592 B
    const int MERGED_SMEM = (64 * WSTR + 3 * ASTG2 + 3 * BSTG2) * 2 + 2 * ZBANK * 4; // 219648 B
    cudaFuncSetAttribute(gemm_kernel,   cudaFuncAttributeMaxDynamicSharedMemorySize, GEMM_SMEM);
    cudaFuncSetAttribute(merged_kernel, cudaFuncAttributeMaxDynamicSharedMemorySize, MERGED_SMEM);

    pack_w_kernel<<<1024, 256>>>(Wi0, 0, D_);
    pack_w_kernel<<<1024, 256>>>(Wh0, 1, H_);
    pack_w_kernel<<<1024, 256>>>(Wi1, 2, H_);
    pack_w_kernel<<<1024, 256>>>(Wh1, 3, H_);
    pack_x_kernel<<<1024, 256>>>(input);
    bias_kernel<<<16, 256>>>(bi0, bh0, bi1, bh1);
    init_state_kernel<<<512, 256>>>(h0, c0);

    gemm_kernel<<<dim3(32, 128), 256, GEMM_SMEM>>>();       // G0
    merged_kernel<<<NB_, 256, MERGED_SMEM>>>(reset, out);   // both layers, wavefront
}

// round 12
// speedup vs baseline: 1.2751x; 1.2751x over previous
#include <cuda_runtime.h>
#include <cuda_fp16.h>
#include <cstdint>
#include <cstddef>

typedef __half f16;

#define T_ 256
#define B_ 64
#define D_ 512
#define H_ 1024
#define G_ 4096
#define TB_ (T_ * B_)
#define OUTS_ (TB_ * H_)
#define NB_ 128          // merged-role CTAs (scheduled first)
#define G0B_ 4096        // G0-role CTAs

// ---------------- device scratch ----------------
__device__ f16   g_Xp  [(size_t)TB_ * D_];
__device__ f16   g_Wi0p[(size_t)G_  * D_];
__device__ f16   g_Wh0p[(size_t)G_  * H_];
__device__ f16   g_Wi1p[(size_t)G_  * H_];
__device__ f16   g_Wh1p[(size_t)G_  * H_];
__device__ float g_b0[G_], g_b1[G_];
__device__ float g_G0[(size_t)TB_ * G_];
__device__ float g_c0s[2 * B_ * H_];
__device__ f16   g_h0p[2][B_ * H_];
__device__ f16   g_h1p[2][B_ * H_];
__device__ unsigned g_bar_grp[8];
__device__ unsigned g_bar_root;
__device__ unsigned g_bar_gen;       // monotonic across replays
__device__ unsigned g_g0_done[128];  // per row-tile completion counters (zeroed each launch)

// ---------------- helpers ----------------
__device__ __forceinline__ void cp_async16(void* sdst, const void* gsrc) {
    uint32_t s = (uint32_t)__cvta_generic_to_shared(sdst);
    asm volatile("cp.async.cg.shared.global [%0], [%1], 16;\n" :: "r"(s), "l"(gsrc));
}
__device__ __forceinline__ void cp_commit() { asm volatile("cp.async.commit_group;\n"); }
template <int N> __device__ __forceinline__ void cp_wait() {
    asm volatile("cp.async.wait_group %0;\n" :: "n"(N));
}
__device__ __forceinline__ unsigned ld_acq(const unsigned* p) {
    unsigned v; asm volatile("ld.acquire.gpu.u32 %0, [%1];" : "=r"(v) : "l"(p)); return v;
}
__device__ __forceinline__ void mma16816(float* d,
    uint32_t a0, uint32_t a1, uint32_t a2, uint32_t a3, uint32_t b0, uint32_t b1)
{
    asm volatile(
        "mma.sync.aligned.m16n8k16.row.col.f32.f16.f16.f32 "
        "{%0,%1,%2,%3},{%4,%5,%6,%7},{%8,%9},{%0,%1,%2,%3};\n"
        : "+f"(d[0]), "+f"(d[1]), "+f"(d[2]), "+f"(d[3])
        : "r"(a0), "r"(a1), "r"(a2), "r"(a3), "r"(b0), "r"(b1));
}
__device__ __forceinline__ void ldsm4(uint32_t& a, uint32_t& b, uint32_t& c, uint32_t& d,
                                      uint32_t addr)
{
    asm volatile("ldmatrix.sync.aligned.m8n8.x4.shared.b16 {%0,%1,%2,%3}, [%4];"
        : "=r"(a), "=r"(b), "=r"(c), "=r"(d) : "r"(addr));
}
__device__ __forceinline__ float sigmoidf_(float z) { return 1.f / (1.f + __expf(-z)); }

// ---------------- packing ----------------
__global__ void pack_w_kernel(const float* __restrict__ src, int which, int K)
{
    f16* dst = (which == 0) ? g_Wi0p : (which == 1) ? g_Wh0p :
               (which == 2) ? g_Wi1p : g_Wh1p;
    int K4 = K >> 2;
    int total = G_ * K4;
    for (int id = blockIdx.x * blockDim.x + threadIdx.x; id < total;
         id += gridDim.x * blockDim.x) {
        int r = id / K4, k4 = (id - r * K4) * 4;
        int sr = (r & 3) * H_ + (r >> 2);
        float4 v = *(const float4*)&src[(size_t)sr * K + k4];
        __half2 a = {__float2half_rn(v.x), __float2half_rn(v.y)};
        __half2 b = {__float2half_rn(v.z), __float2half_rn(v.w)};
        *(uint2*)&dst[(size_t)r * K + k4] = make_uint2(*(uint32_t*)&a, *(uint32_t*)&b);
    }
}

__global__ void pack_x_kernel(const float* __restrict__ src)
{
    int total = TB_ * (D_ >> 2);
    for (int id = blockIdx.x * blockDim.x + threadIdx.x; id < total;
         id += gridDim.x * blockDim.x) {
        int r = id / (D_ >> 2), k4 = (id - r * (D_ >> 2)) * 4;
        float4 v = *(const float4*)&src[(size_t)r * D_ + k4];
        __half2 a = {__float2half_rn(v.x), __float2half_rn(v.y)};
        __half2 b = {__float2half_rn(v.z), __float2half_rn(v.w)};
        *(uint2*)&g_Xp[(size_t)r * D_ + k4] = make_uint2(*(uint32_t*)&a, *(uint32_t*)&b);
    }
}

__global__ void bias_kernel(const float* __restrict__ bi0, const float* __restrict__ bh0,
                            const float* __restrict__ bi1, const float* __restrict__ bh1)
{
    int r = blockIdx.x * blockDim.x + threadIdx.x;
    if (r < 128) g_g0_done[r] = 0u;   // reset producer counters each launch
    if (r < G_) {
        int sr = (r & 3) * H_ + (r >> 2);
        g_b0[r] = bi0[sr] + bh0[sr];
        g_b1[r] = bi1[sr] + bh1[sr];
    }
}

__global__ void init_state_kernel(const float* __restrict__ h0, const float* __restrict__ c0)
{
    int id = blockIdx.x * blockDim.x + threadIdx.x;
    if (id < 2 * B_ * H_) {
        int l = id / (B_ * H_);
        int b = (id / H_) % B_;
        int j = id % H_;
        float hv = h0[(b * 2 + l) * H_ + j];
        g_c0s[id] = c0[(b * 2 + l) * H_ + j];
        f16 hh = __float2half_rn(hv);
        if (l == 0) g_h0p[0][b * H_ + j] = hh;
        else        g_h1p[0][b * H_ + j] = hh;
    }
}

// ---------------- G0-role body: g_G0 tile = Xp @ Wi0p^T + b0, then done++ ----------------
#define GAS 72
__device__ void g0_body(int gid, char* smraw)
{
    f16* sm = (f16*)smraw;
    const int AS = 128 * GAS;
    f16* sA = sm;
    f16* sB = sm + 3 * AS;
    uint32_t sA_u = (uint32_t)__cvta_generic_to_shared(sA);
    uint32_t sB_u = (uint32_t)__cvta_generic_to_shared(sB);

    const f16 *A = g_Xp, *B = g_Wi0p;
    const int K = 512;
    int by = gid >> 5, bx = gid & 31;
    int m0 = by * 128, n0 = bx * 128;

    int tid = threadIdx.x, w = tid >> 5, lane = tid & 31, g = lane >> 2, t4 = lane & 3;
    int wm = w & 1, wn = w >> 1;
    const int NC = K / 64;

    int lr = lane & 15;
    int lcA = (lane >> 4) * 8;
    uint32_t aBase[4], bBase[2];
#pragma unroll
    for (int mt = 0; mt < 4; mt++)
        aBase[mt] = (uint32_t)(((wm * 64 + mt * 16 + lr) * GAS + lcA) * 2);
#pragma unroll
    for (int p = 0; p < 2; p++)
        bBase[p] = (uint32_t)(((wn * 32 + p * 16 + (lane & 7) + ((lane >> 4) & 1) * 8) * GAS
                               + ((lane >> 3) & 1) * 8) * 2);

    float acc[4][4][4];
#pragma unroll
    for (int a = 0; a < 4; a++)
#pragma unroll
        for (int b = 0; b < 4; b++)
#pragma unroll
            for (int c = 0; c < 4; c++) acc[a][b][c] = 0.f;

    auto issue = [&](int c) {
        int k0 = c * 64;
        int st = c % 3;
#pragma unroll
        for (int v = 0; v < 4; v++) {
            int idx = tid + v * 256;
            int r = idx >> 3, s = idx & 7;
            cp_async16(&sA[st * AS + r * GAS + s * 8], &A[(size_t)(m0 + r) * K + k0 + s * 8]);
        }
#pragma unroll
        for (int v = 0; v < 4; v++) {
            int idx = tid + v * 256;
            int r = idx >> 3, s = idx & 7;
            cp_async16(&sB[st * AS + r * GAS + s * 8], &B[(size_t)(n0 + r) * K + k0 + s * 8]);
        }
        cp_commit();
    };

    issue(0); issue(1);
    for (int c = 0; c < NC; c++) {
        if (c + 1 < NC) cp_wait<1>(); else cp_wait<0>();
        __syncthreads();
        if (c + 2 < NC) issue(c + 2);
        uint32_t stA = sA_u + (uint32_t)((c % 3) * AS * 2);
        uint32_t stB = sB_u + (uint32_t)((c % 3) * AS * 2);
#pragma unroll
        for (int kk = 0; kk < 4; kk++) {
            uint32_t kbb = (uint32_t)(kk * 32);
            uint32_t Aa[4][4], Bh[4][2];
#pragma unroll
            for (int mt = 0; mt < 4; mt++)
                ldsm4(Aa[mt][0], Aa[mt][1], Aa[mt][2], Aa[mt][3], stA + aBase[mt] + kbb);
#pragma unroll
            for (int p = 0; p < 2; p++)
                ldsm4(Bh[2 * p][0], Bh[2 * p][1], Bh[2 * p + 1][0], Bh[2 * p + 1][1],
                      stB + bBase[p] + kbb);
#pragma unroll
            for (int mt = 0; mt < 4; mt++)
#pragma unroll
                for (int nt = 0; nt < 4; nt++)
                    mma16816(acc[mt][nt], Aa[mt][0], Aa[mt][1], Aa[mt][2], Aa[mt][3], Bh[nt][0], Bh[nt][1]);
        }
    }

#pragma unroll
    for (int mt = 0; mt < 4; mt++)
#pragma unroll
        for (int nt = 0; nt < 4; nt++) {
            int row = m0 + wm * 64 + mt * 16 + g;
            int col = n0 + wn * 32 + nt * 8 + 2 * t4;
            float ba = g_b0[col], bb = g_b0[col + 1];
            *(float2*)&g_G0[(size_t)row * G_ + col] =
                make_float2(acc[mt][nt][0] + ba, acc[mt][nt][1] + bb);
            *(float2*)&g_G0[(size_t)(row + 8) * G_ + col] =
                make_float2(acc[mt][nt][2] + ba, acc[mt][nt][3] + bb);
        }

    __threadfence();
    __syncthreads();
    if (tid == 0) atomicAdd(&g_g0_done[by], 1u);
}

// ---------------- merged-role body (R10 wavefront) ----------------
#define WSTR 1032
#define ASTR 136
#define ASTG (64 * ASTR)
#define BSTG (32 * ASTR)
#define ZBANK (64 * 36)
#define MERGED_SMEM ((64 * WSTR + 3 * ASTG + 3 * BSTG) * 2 + 2 * ZBANK * 4)   // 228864 B

__device__ void merged_body(int rbid, const int* __restrict__ reset,
                            float* __restrict__ out, char* smraw)
{
    f16* smem = (f16*)smraw;
    f16* sW0 = smem;
    f16* sW1 = smem + 32 * WSTR;
    f16* sA  = smem + 64 * WSTR;
    f16* sB  = sA + 3 * ASTG;
    float* zs = (float*)(sB + 3 * BSTG);
    uint32_t sW0_u = (uint32_t)__cvta_generic_to_shared(sW0);
    uint32_t sW1_u = (uint32_t)__cvta_generic_to_shared(sW1);
    uint32_t sA_u  = (uint32_t)__cvta_generic_to_shared(sA);
    uint32_t sB_u  = (uint32_t)__cvta_generic_to_shared(sB);

    int tid = threadIdx.x, w = tid >> 5, lane = tid & 31, g = lane >> 2, t4 = lane & 3;
    int wk = w & 1, wn = (w >> 1) & 1, wm = w >> 2;
    int n0 = rbid * 32;
    unsigned gen0 = ld_acq(&g_bar_gen);

    for (int i = tid; i < 32 * 128; i += 256) {
        int r = i >> 7, sseg = i & 127;
        *(uint4*)&sW0[r * WSTR + sseg * 8] = *(const uint4*)&g_Wh0p[(size_t)(n0 + r) * H_ + sseg * 8];
        *(uint4*)&sW1[r * WSTR + sseg * 8] = *(const uint4*)&g_Wh1p[(size_t)(n0 + r) * H_ + sseg * 8];
    }

    int lr = lane & 15;
    int lcA = (lane >> 4) * 8;
    uint32_t aBase[2];
    aBase[0] = (uint32_t)(((wm * 32 + 0 + lr) * ASTR + lcA) * 2);
    aBase[1] = (uint32_t)(((wm * 32 + 16 + lr) * ASTR + lcA) * 2);
    uint32_t wBase[2], bBaseS[2];
#pragma unroll
    for (int nt = 0; nt < 2; nt++) {
        wBase[nt]  = (uint32_t)(((wn * 16 + nt * 8 + (lane & 7)) * WSTR
                                 + ((lane >> 3) & 1) * 8 + ((lane >> 4) & 1) * 16) * 2);
        bBaseS[nt] = (uint32_t)(((wn * 16 + nt * 8 + (lane & 7)) * ASTR
                                 + ((lane >> 3) & 1) * 8 + ((lane >> 4) & 1) * 16) * 2);
    }

    int bb = tid >> 3, jl = tid & 7, j = rbid * 8 + jl;
    int bb2 = (tid + 256) >> 3;
    int wrow[4] = { wm * 32 + g, wm * 32 + 8 + g, wm * 32 + 16 + g, wm * 32 + 24 + g };

    float c0r[2], c1r[2];
    c0r[0] = g_c0s[(0 * B_ + bb) * H_ + j];
    c0r[1] = g_c0s[(0 * B_ + bb2) * H_ + j];
    c1r[0] = g_c0s[(1 * B_ + bb) * H_ + j];
    c1r[1] = g_c0s[(1 * B_ + bb2) * H_ + j];

    float4 b1v = *(const float4*)&g_b1[n0 + 4 * jl];

    float rst0[2], rst1[2], kw[4];
    rst0[0] = (float)reset[bb];
    rst0[1] = (float)reset[bb2];
    rst1[0] = rst1[1] = 0.f;
    kw[0] = kw[1] = kw[2] = kw[3] = 1.f;

    // wait for G0 row-tile 0 (t=0,1) then load initial gp
    if (tid == 0) { while (ld_acq(&g_g0_done[0]) < 32u) { } }
    __syncthreads();
    float4 gp[2];
    gp[0] = *(const float4*)&g_G0[(size_t)bb * G_ + n0 + 4 * jl];
    gp[1] = *(const float4*)&g_G0[(size_t)bb2 * G_ + n0 + 4 * jl];

    for (int s = 0; s <= T_; s++) {
        const f16* A0 = g_h0p[s & 1];          // h0_{s-1}
        const f16* A1 = g_h1p[(s + 1) & 1];    // h1_{s-2}

        float acc0[2][2][4], accWi[2][2][4];
#pragma unroll
        for (int a = 0; a < 2; a++)
#pragma unroll
            for (int b = 0; b < 2; b++)
#pragma unroll
                for (int c = 0; c < 4; c++) { acc0[a][b][c] = 0.f; accWi[a][b][c] = 0.f; }

        auto issueF = [&](int c) {
            int k0 = c * 128, st = c % 3;
#pragma unroll
            for (int v = 0; v < 4; v++) {
                int idx = tid + v * 256;
                int r = idx >> 4, sseg = idx & 15;
                cp_async16(&sA[st * ASTG + r * ASTR + sseg * 8], &A0[(size_t)r * H_ + k0 + sseg * 8]);
            }
#pragma unroll
            for (int v = 0; v < 2; v++) {
                int idx = tid + v * 256;
                int r = idx >> 4, sseg = idx & 15;
                cp_async16(&sB[st * BSTG + r * ASTR + sseg * 8],
                           &g_Wi1p[(size_t)(n0 + r) * H_ + k0 + sseg * 8]);
            }
            cp_commit();
        };
        auto issueH = [&](int c) {
            int k0 = c * 128, st = c % 3;
#pragma unroll
            for (int v = 0; v < 4; v++) {
                int idx = tid + v * 256;
                int r = idx >> 4, sseg = idx & 15;
                cp_async16(&sA[st * ASTG + r * ASTR + sseg * 8], &A1[(size_t)r * H_ + k0 + sseg * 8]);
            }
            cp_commit();
        };

        issueF(0); issueF(1);
        for (int c = 0; c < 8; c++) {
            if (c + 1 < 8) cp_wait<1>(); else cp_wait<0>();
            __syncthreads();
            if (c + 2 < 8) issueF(c + 2);
            else if (c == 7 && s >= 1) issueH(0);   // stage 0 free (chunk 6 consumed)
            uint32_t stA = sA_u + (uint32_t)((c % 3) * ASTG * 2);
            uint32_t stB = sB_u + (uint32_t)((c % 3) * BSTG * 2);
            uint32_t wOffC = (uint32_t)(c * 128 * 2);
#pragma unroll
            for (int kpi = 0; kpi < 2; kpi++) {
                int kp = kpi * 2 + wk;
                uint32_t kpb = (uint32_t)(kp * 64);
                uint32_t Bq0[2][4], BqW[2][4];
#pragma unroll
                for (int nt = 0; nt < 2; nt++) {
                    ldsm4(Bq0[nt][0], Bq0[nt][1], Bq0[nt][2], Bq0[nt][3],
                          sW0_u + wBase[nt] + wOffC + kpb);
                    ldsm4(BqW[nt][0], BqW[nt][1], BqW[nt][2], BqW[nt][3],
                          stB + bBaseS[nt] + kpb);
                }
#pragma unroll
                for (int h = 0; h < 2; h++) {
                    uint32_t kbb = kpb + (uint32_t)(h * 32);
                    uint32_t Aa[2][4];
#pragma unroll
                    for (int mt = 0; mt < 2; mt++)
                        ldsm4(Aa[mt][0], Aa[mt][1], Aa[mt][2], Aa[mt][3], stA + aBase[mt] + kbb);
#pragma unroll
                    for (int mt = 0; mt < 2; mt++)
#pragma unroll
                        for (int nt = 0; nt < 2; nt++) {
                            mma16816(acc0[mt][nt], Aa[mt][0], Aa[mt][1], Aa[mt][2], Aa[mt][3],
                                     Bq0[nt][h * 2], Bq0[nt][h * 2 + 1]);
                            mma16816(accWi[mt][nt], Aa[mt][0], Aa[mt][1], Aa[mt][2], Aa[mt][3],
                                     BqW[nt][h * 2], BqW[nt][h * 2 + 1]);
                        }
                }
            }
        }

        // layer0 partials -> zs
        {
            float* zb = zs + wk * ZBANK;
#pragma unroll
            for (int mt = 0; mt < 2; mt++)
#pragma unroll
                for (int nt = 0; nt < 2; nt++) {
                    int r0 = wm * 32 + mt * 16 + g;
                    int c0 = wn * 16 + nt * 8 + 2 * t4;
                    zb[r0 * 36 + c0]     = acc0[mt][nt][0];
                    zb[r0 * 36 + c0 + 1] = acc0[mt][nt][1];
                    zb[(r0 + 8) * 36 + c0]     = acc0[mt][nt][2];
                    zb[(r0 + 8) * 36 + c0 + 1] = acc0[mt][nt][3];
                }
        }
        __syncthreads();

        if (s >= 1) issueH(1);    // stage 1 free now (chunk 7 consumed by all warps)

        // tail0
        if (s < T_) {
#pragma unroll
            for (int it = 0; it < 2; it++) {
                int b = it ? bb2 : bb;
                float keep = 1.0f - rst0[it];
                int zi_i = b * 36 + 4 * jl;
                float zi = gp[it].x + keep * (zs[zi_i + 0] + zs[ZBANK + zi_i + 0]);
                float zf = gp[it].y + keep * (zs[zi_i + 1] + zs[ZBANK + zi_i + 1]);
                float zg = gp[it].z + keep * (zs[zi_i + 2] + zs[ZBANK + zi_i + 2]);
                float zo = gp[it].w + keep * (zs[zi_i + 3] + zs[ZBANK + zi_i + 3]);
                float cn = sigmoidf_(zf) * keep * c0r[it] + sigmoidf_(zi) * tanhf(zg);
                float hn = sigmoidf_(zo) * tanhf(cn);
                c0r[it] = cn;
                g_h0p[(s + 1) & 1][b * H_ + j] = __float2half_rn(hn);
                if (s == T_ - 1) {
                    out[OUTS_ + (b * 2 + 0) * H_ + j] = hn;
                    out[OUTS_ + 2 * B_ * H_ + (b * 2 + 0) * H_ + j] = cn;
                }
            }
        }

        float hn_s[2], cn_s[2];
        if (s >= 1) {
            float accWh[2][2][4];
#pragma unroll
            for (int a = 0; a < 2; a++)
#pragma unroll
                for (int b = 0; b < 2; b++)
#pragma unroll
                    for (int c = 0; c < 4; c++) accWh[a][b][c] = 0.f;

            for (int c = 0; c < 8; c++) {
                if (c + 1 < 8) cp_wait<1>(); else cp_wait<0>();
                __syncthreads();
                if (c + 2 < 8) issueH(c + 2);
                uint32_t stA = sA_u + (uint32_t)((c % 3) * ASTG * 2);
                uint32_t wOffC = (uint32_t)(c * 128 * 2);
#pragma unroll
                for (int kpi = 0; kpi < 2; kpi++) {
                    int kp = kpi * 2 + wk;
                    uint32_t kpb = (uint32_t)(kp * 64);
                    uint32_t Bq1[2][4];
#pragma unroll
                    for (int nt = 0; nt < 2; nt++)
                        ldsm4(Bq1[nt][0], Bq1[nt][1], Bq1[nt][2], Bq1[nt][3],
                              sW1_u + wBase[nt] + wOffC + kpb);
#pragma unroll
                    for (int h = 0; h < 2; h++) {
                        uint32_t kbb = kpb + (uint32_t)(h * 32);
                        uint32_t Aa[2][4];
#pragma unroll
                        for (int mt = 0; mt < 2; mt++)
                            ldsm4(Aa[mt][0], Aa[mt][1], Aa[mt][2], Aa[mt][3], stA + aBase[mt] + kbb);
#pragma unroll
                        for (int mt = 0; mt < 2; mt++)
#pragma unroll
                            for (int nt = 0; nt < 2; nt++)
                                mma16816(accWh[mt][nt], Aa[mt][0], Aa[mt][1], Aa[mt][2], Aa[mt][3],
                                         Bq1[nt][h * 2], Bq1[nt][h * 2 + 1]);
                    }
                }
            }

            {
                float* zb = zs + wk * ZBANK;
#pragma unroll
                for (int mt = 0; mt < 2; mt++)
#pragma unroll
                    for (int nt = 0; nt < 2; nt++) {
                        int r0 = wm * 32 + mt * 16 + g;
                        int c0 = wn * 16 + nt * 8 + 2 * t4;
                        float k0f = kw[mt * 2 + 0], k1f = kw[mt * 2 + 1];
                        zb[r0 * 36 + c0]     = k0f * accWh[mt][nt][0] + accWi[mt][nt][0];
                        zb[r0 * 36 + c0 + 1] = k0f * accWh[mt][nt][1] + accWi[mt][nt][1];
                        zb[(r0 + 8) * 36 + c0]     = k1f * accWh[mt][nt][2] + accWi[mt][nt][2];
                        zb[(r0 + 8) * 36 + c0 + 1] = k1f * accWh[mt][nt][3] + accWi[mt][nt][3];
                    }
            }
            __syncthreads();

            // tail1
#pragma unroll
            for (int it = 0; it < 2; it++) {
                int b = it ? bb2 : bb;
                float keep = 1.0f - rst1[it];
                int zi_i = b * 36 + 4 * jl;
                float zi = b1v.x + (zs[zi_i + 0] + zs[ZBANK + zi_i + 0]);
                float zf = b1v.y + (zs[zi_i + 1] + zs[ZBANK + zi_i + 1]);
                float zg = b1v.z + (zs[zi_i + 2] + zs[ZBANK + zi_i + 2]);
                float zo = b1v.w + (zs[zi_i + 3] + zs[ZBANK + zi_i + 3]);
                float cn = sigmoidf_(zf) * keep * c1r[it] + sigmoidf_(zi) * tanhf(zg);
                float hn = sigmoidf_(zo) * tanhf(cn);
                c1r[it] = cn; cn_s[it] = cn; hn_s[it] = hn;
                g_h1p[s & 1][b * H_ + j] = __float2half_rn(hn);
                if (s == T_) {
                    out[OUTS_ + (b * 2 + 1) * H_ + j] = hn;
                    out[OUTS_ + 2 * B_ * H_ + (b * 2 + 1) * H_ + j] = cn;
                }
            }
        }

        // barrier arrive
        __syncthreads();
        if (tid == 0) {
            __threadfence();
            unsigned grp = (unsigned)rbid >> 4;
            if (atomicAdd(&g_bar_grp[grp], 1u) == 15u) {
                g_bar_grp[grp] = 0u;
                if (atomicAdd(&g_bar_root, 1u) == 7u) {
                    g_bar_root = 0u;
                    __threadfence();
                    g_bar_gen = gen0 + s + 1;
                }
            }
        }

        // overlap: output stores + reset/kw prefetch
        if (s >= 1) {
            int t1 = s - 1;
#pragma unroll
            for (int it = 0; it < 2; it++) {
                int b = it ? bb2 : bb;
                out[(size_t)t1 * B_ * H_ + b * H_ + j] = hn_s[it];
            }
        }
        if (s + 1 <= T_) {
            rst1[0] = rst0[0]; rst1[1] = rst0[1];
            if (s + 1 < T_) {
                rst0[0] = (float)reset[(s + 1) * B_ + bb];
                rst0[1] = (float)reset[(s + 1) * B_ + bb2];
            }
#pragma unroll
            for (int i = 0; i < 4; i++)
                kw[i] = 1.0f - (float)reset[s * B_ + wrow[i]];
        }

        // barrier wait + G0-producer wait for next row-tile
        if (tid == 0) {
            while (ld_acq(&g_bar_gen) < gen0 + s + 1) { }
            if (s + 1 < T_) {
                unsigned by2 = (unsigned)(s + 1) >> 1;
                while (ld_acq(&g_g0_done[by2]) < 32u) { }
            }
        }
        __syncthreads();

        // gp prefetch for step s+1 (consumed a full step later)
        if (s + 1 < T_) {
            gp[0] = *(const float4*)&g_G0[((size_t)(s + 1) * B_ + bb) * G_ + n0 + 4 * jl];
            gp[1] = *(const float4*)&g_G0[((size_t)(s + 1) * B_ + bb2) * G_ + n0 + 4 * jl];
        }
    }
}

// ---------------- fused kernel: merged CTAs first, G0 producers after ----------------
__global__ __launch_bounds__(256, 1) void fused_kernel(const int* __restrict__ reset,
                                                       float* __restrict__ out)
{
    extern __shared__ char smraw[];
    int bid = blockIdx.x;
    if (bid < NB_) merged_body(bid, reset, out, smraw);
    else           g0_body(bid - NB_, smraw);
}

// ---------------- launch ----------------
extern "C" void kernel_launch(void* const* d_in, const int* in_sizes, int n_in,
                              void* d_out, int out_size)
{
    (void)in_sizes; (void)n_in; (void)out_size;
    const float* input = (const float*)d_in[0];
    const int*   reset = (const int*)d_in[1];
    const float* h0    = (const float*)d_in[2];
    const float* c0    = (const float*)d_in[3];
    const float* Wi0   = (const float*)d_in[4];
    const float* Wh0   = (const float*)d_in[5];
    const float* bi0   = (const float*)d_in[6];
    const float* bh0   = (const float*)d_in[7];
    const float* Wi1   = (const float*)d_in[8];
    const float* Wh1   = (const float*)d_in[9];
    const float* bi1   = (const float*)d_in[10];
    const float* bh1   = (const float*)d_in[11];
    float* out = (float*)d_out;

    cudaFuncSetAttribute(fused_kernel, cudaFuncAttributeMaxDynamicSharedMemorySize, MERGED_SMEM);

    pack_w_kernel<<<1024, 256>>>(Wi0, 0, D_);
    pack_w_kernel<<<1024, 256>>>(Wh0, 1, H_);
    pack_w_kernel<<<1024, 256>>>(Wi1, 2, H_);
    pack_w_kernel<<<1024, 256>>>(Wh1, 3, H_);
    pack_x_kernel<<<1024, 256>>>(input);
    bias_kernel<<<16, 256>>>(bi0, bh0, bi1, bh1);
    init_state_kernel<<<512, 256>>>(h0, c0);

    fused_kernel<<<NB_ + G0B_, 256, MERGED_SMEM>>>(reset, out);
}

// round 13
// speedup vs baseline: 1.3427x; 1.0530x over previous
#include <cuda_runtime.h>
#include <cuda_fp16.h>
#include <cstdint>
#include <cstddef>

typedef __half f16;

#define T_ 256
#define B_ 64
#define D_ 512
#define H_ 1024
#define G_ 4096
#define TB_ (T_ * B_)
#define OUTS_ (TB_ * H_)
#define NB_ 128          // merged-role CTAs (scheduled first)
#define G0B_ 4096        // G0-role CTAs

// ---------------- device scratch ----------------
__device__ f16   g_Xp  [(size_t)TB_ * D_];
__device__ f16   g_Wi0p[(size_t)G_  * D_];
__device__ f16   g_Wh0p[(size_t)G_  * H_];
__device__ f16   g_Wi1p[(size_t)G_  * H_];
__device__ f16   g_Wh1p[(size_t)G_  * H_];
__device__ float g_b0[G_], g_b1[G_];
__device__ float g_G0[(size_t)TB_ * G_];
__device__ float g_c0s[2 * B_ * H_];
__device__ f16   g_h0p[2][B_ * H_];
__device__ f16   g_h1p[2][B_ * H_];
__device__ unsigned g_bar_grp[8];
__device__ unsigned g_bar_root;
__device__ unsigned g_bar_gen;       // monotonic across replays
__device__ unsigned g_g0_done[128];  // per row-tile completion counters (cleared in setup)

// ---------------- helpers ----------------
__device__ __forceinline__ void cp_async16(void* sdst, const void* gsrc) {
    uint32_t s = (uint32_t)__cvta_generic_to_shared(sdst);
    asm volatile("cp.async.cg.shared.global [%0], [%1], 16;\n" :: "r"(s), "l"(gsrc));
}
__device__ __forceinline__ void cp_commit() { asm volatile("cp.async.commit_group;\n"); }
template <int N> __device__ __forceinline__ void cp_wait() {
    asm volatile("cp.async.wait_group %0;\n" :: "n"(N));
}
__device__ __forceinline__ unsigned ld_acq(const unsigned* p) {
    unsigned v; asm volatile("ld.acquire.gpu.u32 %0, [%1];" : "=r"(v) : "l"(p)); return v;
}
__device__ __forceinline__ void mma16816(float* d,
    uint32_t a0, uint32_t a1, uint32_t a2, uint32_t a3, uint32_t b0, uint32_t b1)
{
    asm volatile(
        "mma.sync.aligned.m16n8k16.row.col.f32.f16.f16.f32 "
        "{%0,%1,%2,%3},{%4,%5,%6,%7},{%8,%9},{%0,%1,%2,%3};\n"
        : "+f"(d[0]), "+f"(d[1]), "+f"(d[2]), "+f"(d[3])
        : "r"(a0), "r"(a1), "r"(a2), "r"(a3), "r"(b0), "r"(b1));
}
__device__ __forceinline__ void ldsm4(uint32_t& a, uint32_t& b, uint32_t& c, uint32_t& d,
                                      uint32_t addr)
{
    asm volatile("ldmatrix.sync.aligned.m8n8.x4.shared.b16 {%0,%1,%2,%3}, [%4];"
        : "=r"(a), "=r"(b), "=r"(c), "=r"(d) : "r"(addr));
}
__device__ __forceinline__ float sigmoidf_(float z) {
    return __fdividef(1.f, 1.f + __expf(-z));
}
__device__ __forceinline__ float tanhf_(float z) {
    return __fdividef(2.f, 1.f + __expf(-2.f * z)) - 1.f;
}

// ---------------- unified setup kernel ----------------
// block ranges: [0,256) Wi0 | [256,768) Wh0 | [768,1280) Wi1 | [1280,1792) Wh1
//               [1792,2816) Xp | [2816,2832) bias+flags | [2832,2848) init
__global__ void setup_kernel(const float* __restrict__ input,
                             const float* __restrict__ h0, const float* __restrict__ c0,
                             const float* __restrict__ Wi0, const float* __restrict__ Wh0,
                             const float* __restrict__ bi0, const float* __restrict__ bh0,
                             const float* __restrict__ Wi1, const float* __restrict__ Wh1,
                             const float* __restrict__ bi1, const float* __restrict__ bh1)
{
    int blk = blockIdx.x;
    int tid = threadIdx.x;

    if (blk < 1792) {
        const float* src; f16* dst; int K, base_blk, nblk;
        if (blk < 256)       { src = Wi0; dst = g_Wi0p; K = D_; base_blk = 0;    nblk = 256; }
        else if (blk < 768)  { src = Wh0; dst = g_Wh0p; K = H_; base_blk = 256;  nblk = 512; }
        else if (blk < 1280) { src = Wi1; dst = g_Wi1p; K = H_; base_blk = 768;  nblk = 512; }
        else                 { src = Wh1; dst = g_Wh1p; K = H_; base_blk = 1280; nblk = 512; }
        int K4 = K >> 2;
        int total = G_ * K4;
        for (int id = (blk - base_blk) * 256 + tid; id < total; id += nblk * 256) {
            int r = id / K4, k4 = (id - r * K4) * 4;
            int sr = (r & 3) * H_ + (r >> 2);
            float4 v = *(const float4*)&src[(size_t)sr * K + k4];
            __half2 a = {__float2half_rn(v.x), __float2half_rn(v.y)};
            __half2 b = {__float2half_rn(v.z), __float2half_rn(v.w)};
            *(uint2*)&dst[(size_t)r * K + k4] = make_uint2(*(uint32_t*)&a, *(uint32_t*)&b);
        }
    } else if (blk < 2816) {
        int total = TB_ * (D_ >> 2);
        for (int id = (blk - 1792) * 256 + tid; id < total; id += 1024 * 256) {
            int r = id / (D_ >> 2), k4 = (id - r * (D_ >> 2)) * 4;
            float4 v = *(const float4*)&input[(size_t)r * D_ + k4];
            __half2 a = {__float2half_rn(v.x), __float2half_rn(v.y)};
            __half2 b = {__float2half_rn(v.z), __float2half_rn(v.w)};
            *(uint2*)&g_Xp[(size_t)r * D_ + k4] = make_uint2(*(uint32_t*)&a, *(uint32_t*)&b);
        }
    } else if (blk < 2832) {
        int r = (blk - 2816) * 256 + tid;
        if (r < 128) g_g0_done[r] = 0u;
        if (r < G_) {
            int sr = (r & 3) * H_ + (r >> 2);
            g_b0[r] = bi0[sr] + bh0[sr];
            g_b1[r] = bi1[sr] + bh1[sr];
        }
    } else {
        for (int id = (blk - 2832) * 256 + tid; id < 2 * B_ * H_; id += 16 * 256) {
            int l = id / (B_ * H_);
            int b = (id / H_) % B_;
            int j = id % H_;
            float hv = h0[(b * 2 + l) * H_ + j];
            g_c0s[id] = c0[(b * 2 + l) * H_ + j];
            f16 hh = __float2half_rn(hv);
            if (l == 0) g_h0p[0][b * H_ + j] = hh;
            else        g_h1p[0][b * H_ + j] = hh;
        }
    }
}

// ---------------- G0-role body: g_G0 tile = Xp @ Wi0p^T + b0, then done++ ----------------
#define GAS 72
__device__ void g0_body(int gid, char* smraw)
{
    f16* sm = (f16*)smraw;
    const int AS = 128 * GAS;
    f16* sA = sm;
    f16* sB = sm + 3 * AS;
    uint32_t sA_u = (uint32_t)__cvta_generic_to_shared(sA);
    uint32_t sB_u = (uint32_t)__cvta_generic_to_shared(sB);

    const f16 *A = g_Xp, *B = g_Wi0p;
    const int K = 512;
    int by = gid >> 5, bx = gid & 31;
    int m0 = by * 128, n0 = bx * 128;

    int tid = threadIdx.x, w = tid >> 5, lane = tid & 31, g = lane >> 2, t4 = lane & 3;
    int wm = w & 1, wn = w >> 1;
    const int NC = K / 64;

    int lr = lane & 15;
    int lcA = (lane >> 4) * 8;
    uint32_t aBase[4], bBase[2];
#pragma unroll
    for (int mt = 0; mt < 4; mt++)
        aBase[mt] = (uint32_t)(((wm * 64 + mt * 16 + lr) * GAS + lcA) * 2);
#pragma unroll
    for (int p = 0; p < 2; p++)
        bBase[p] = (uint32_t)(((wn * 32 + p * 16 + (lane & 7) + ((lane >> 4) & 1) * 8) * GAS
                               + ((lane >> 3) & 1) * 8) * 2);

    float acc[4][4][4];
#pragma unroll
    for (int a = 0; a < 4; a++)
#pragma unroll
        for (int b = 0; b < 4; b++)
#pragma unroll
            for (int c = 0; c < 4; c++) acc[a][b][c] = 0.f;

    auto issue = [&](int c) {
        int k0 = c * 64;
        int st = c % 3;
#pragma unroll
        for (int v = 0; v < 4; v++) {
            int idx = tid + v * 256;
            int r = idx >> 3, s = idx & 7;
            cp_async16(&sA[st * AS + r * GAS + s * 8], &A[(size_t)(m0 + r) * K + k0 + s * 8]);
        }
#pragma unroll
        for (int v = 0; v < 4; v++) {
            int idx = tid + v * 256;
            int r = idx >> 3, s = idx & 7;
            cp_async16(&sB[st * AS + r * GAS + s * 8], &B[(size_t)(n0 + r) * K + k0 + s * 8]);
        }
        cp_commit();
    };

    issue(0); issue(1);
    for (int c = 0; c < NC; c++) {
        if (c + 1 < NC) cp_wait<1>(); else cp_wait<0>();
        __syncthreads();
        if (c + 2 < NC) issue(c + 2);
        uint32_t stA = sA_u + (uint32_t)((c % 3) * AS * 2);
        uint32_t stB = sB_u + (uint32_t)((c % 3) * AS * 2);
#pragma unroll
        for (int kk = 0; kk < 4; kk++) {
            uint32_t kbb = (uint32_t)(kk * 32);
            uint32_t Aa[4][4], Bh[4][2];
#pragma unroll
            for (int mt = 0; mt < 4; mt++)
                ldsm4(Aa[mt][0], Aa[mt][1], Aa[mt][2], Aa[mt][3], stA + aBase[mt] + kbb);
#pragma unroll
            for (int p = 0; p < 2; p++)
                ldsm4(Bh[2 * p][0], Bh[2 * p][1], Bh[2 * p + 1][0], Bh[2 * p + 1][1],
                      stB + bBase[p] + kbb);
#pragma unroll
            for (int mt = 0; mt < 4; mt++)
#pragma unroll
                for (int nt = 0; nt < 4; nt++)
                    mma16816(acc[mt][nt], Aa[mt][0], Aa[mt][1], Aa[mt][2], Aa[mt][3], Bh[nt][0], Bh[nt][1]);
        }
    }

#pragma unroll
    for (int mt = 0; mt < 4; mt++)
#pragma unroll
        for (int nt = 0; nt < 4; nt++) {
            int row = m0 + wm * 64 + mt * 16 + g;
            int col = n0 + wn * 32 + nt * 8 + 2 * t4;
            float ba = g_b0[col], bb = g_b0[col + 1];
            *(float2*)&g_G0[(size_t)row * G_ + col] =
                make_float2(acc[mt][nt][0] + ba, acc[mt][nt][1] + bb);
            *(float2*)&g_G0[(size_t)(row + 8) * G_ + col] =
                make_float2(acc[mt][nt][2] + ba, acc[mt][nt][3] + bb);
        }

    __threadfence();
    __syncthreads();
    if (tid == 0) atomicAdd(&g_g0_done[by], 1u);
}

// ---------------- merged-role body (wavefront) ----------------
#define WSTR 1032
#define ASTR 136
#define ASTG (64 * ASTR)
#define BSTG (32 * ASTR)
#define ZBANK (64 * 36)
#define MERGED_SMEM ((64 * WSTR + 3 * ASTG + 3 * BSTG) * 2 + 2 * ZBANK * 4)   // 228864 B

__device__ void merged_body(int rbid, const int* __restrict__ reset,
                            float* __restrict__ out, char* smraw)
{
    f16* smem = (f16*)smraw;
    f16* sW0 = smem;
    f16* sW1 = smem + 32 * WSTR;
    f16* sA  = smem + 64 * WSTR;
    f16* sB  = sA + 3 * ASTG;
    float* zs = (float*)(sB + 3 * BSTG);
    uint32_t sW0_u = (uint32_t)__cvta_generic_to_shared(sW0);
    uint32_t sW1_u = (uint32_t)__cvta_generic_to_shared(sW1);
    uint32_t sA_u  = (uint32_t)__cvta_generic_to_shared(sA);
    uint32_t sB_u  = (uint32_t)__cvta_generic_to_shared(sB);

    int tid = threadIdx.x, w = tid >> 5, lane = tid & 31, g = lane >> 2, t4 = lane & 3;
    int wk = w & 1, wn = (w >> 1) & 1, wm = w >> 2;
    int n0 = rbid * 32;
    unsigned gen0 = ld_acq(&g_bar_gen);

    for (int i = tid; i < 32 * 128; i += 256) {
        int r = i >> 7, sseg = i & 127;
        *(uint4*)&sW0[r * WSTR + sseg * 8] = *(const uint4*)&g_Wh0p[(size_t)(n0 + r) * H_ + sseg * 8];
        *(uint4*)&sW1[r * WSTR + sseg * 8] = *(const uint4*)&g_Wh1p[(size_t)(n0 + r) * H_ + sseg * 8];
    }

    int lr = lane & 15;
    int lcA = (lane >> 4) * 8;
    uint32_t aBase[2];
    aBase[0] = (uint32_t)(((wm * 32 + 0 + lr) * ASTR + lcA) * 2);
    aBase[1] = (uint32_t)(((wm * 32 + 16 + lr) * ASTR + lcA) * 2);
    uint32_t wBase[2], bBaseS[2];
#pragma unroll
    for (int nt = 0; nt < 2; nt++) {
        wBase[nt]  = (uint32_t)(((wn * 16 + nt * 8 + (lane & 7)) * WSTR
                                 + ((lane >> 3) & 1) * 8 + ((lane >> 4) & 1) * 16) * 2);
        bBaseS[nt] = (uint32_t)(((wn * 16 + nt * 8 + (lane & 7)) * ASTR
                                 + ((lane >> 3) & 1) * 8 + ((lane >> 4) & 1) * 16) * 2);
    }

    int bb = tid >> 3, jl = tid & 7, j = rbid * 8 + jl;
    int bb2 = (tid + 256) >> 3;
    int wrow[4] = { wm * 32 + g, wm * 32 + 8 + g, wm * 32 + 16 + g, wm * 32 + 24 + g };

    float c0r[2], c1r[2];
    c0r[0] = g_c0s[(0 * B_ + bb) * H_ + j];
    c0r[1] = g_c0s[(0 * B_ + bb2) * H_ + j];
    c1r[0] = g_c0s[(1 * B_ + bb) * H_ + j];
    c1r[1] = g_c0s[(1 * B_ + bb2) * H_ + j];

    float4 b1v = *(const float4*)&g_b1[n0 + 4 * jl];

    float rst0[2], rst1[2], kw[4];
    rst0[0] = (float)reset[bb];
    rst0[1] = (float)reset[bb2];
    rst1[0] = rst1[1] = 0.f;
    kw[0] = kw[1] = kw[2] = kw[3] = 1.f;

    // wait for G0 row-tile 0 (t=0,1) then load initial gp
    if (tid == 0) { while (ld_acq(&g_g0_done[0]) < 32u) { } }
    __syncthreads();
    float4 gp[2];
    gp[0] = __ldcs((const float4*)&g_G0[(size_t)bb * G_ + n0 + 4 * jl]);
    gp[1] = __ldcs((const float4*)&g_G0[(size_t)bb2 * G_ + n0 + 4 * jl]);

    for (int s = 0; s <= T_; s++) {
        const f16* A0 = g_h0p[s & 1];          // h0_{s-1}
        const f16* A1 = g_h1p[(s + 1) & 1];    // h1_{s-2}

        float acc0[2][2][4], accWi[2][2][4];
#pragma unroll
        for (int a = 0; a < 2; a++)
#pragma unroll
            for (int b = 0; b < 2; b++)
#pragma unroll
                for (int c = 0; c < 4; c++) { acc0[a][b][c] = 0.f; accWi[a][b][c] = 0.f; }

        auto issueF = [&](int c) {
            int k0 = c * 128, st = c % 3;
#pragma unroll
            for (int v = 0; v < 4; v++) {
                int idx = tid + v * 256;
                int r = idx >> 4, sseg = idx & 15;
                cp_async16(&sA[st * ASTG + r * ASTR + sseg * 8], &A0[(size_t)r * H_ + k0 + sseg * 8]);
            }
#pragma unroll
            for (int v = 0; v < 2; v++) {
                int idx = tid + v * 256;
                int r = idx >> 4, sseg = idx & 15;
                cp_async16(&sB[st * BSTG + r * ASTR + sseg * 8],
                           &g_Wi1p[(size_t)(n0 + r) * H_ + k0 + sseg * 8]);
            }
            cp_commit();
        };
        auto issueH = [&](int c) {
            int k0 = c * 128, st = c % 3;
#pragma unroll
            for (int v = 0; v < 4; v++) {
                int idx = tid + v * 256;
                int r = idx >> 4, sseg = idx & 15;
                cp_async16(&sA[st * ASTG + r * ASTR + sseg * 8], &A1[(size_t)r * H_ + k0 + sseg * 8]);
            }
            cp_commit();
        };

        issueF(0); issueF(1);
        for (int c = 0; c < 8; c++) {
            if (c + 1 < 8) cp_wait<1>(); else cp_wait<0>();
            __syncthreads();
            if (c + 2 < 8) issueF(c + 2);
            else if (c == 7 && s >= 1) issueH(0);
            uint32_t stA = sA_u + (uint32_t)((c % 3) * ASTG * 2);
            uint32_t stB = sB_u + (uint32_t)((c % 3) * BSTG * 2);
            uint32_t wOffC = (uint32_t)(c * 128 * 2);
#pragma unroll
            for (int kpi = 0; kpi < 2; kpi++) {
                int kp = kpi * 2 + wk;
                uint32_t kpb = (uint32_t)(kp * 64);
                uint32_t Bq0[2][4], BqW[2][4];
#pragma unroll
                for (int nt = 0; nt < 2; nt++) {
                    ldsm4(Bq0[nt][0], Bq0[nt][1], Bq0[nt][2], Bq0[nt][3],
                          sW0_u + wBase[nt] + wOffC + kpb);
                    ldsm4(BqW[nt][0], BqW[nt][1], BqW[nt][2], BqW[nt][3],
                          stB + bBaseS[nt] + kpb);
                }
#pragma unroll
                for (int h = 0; h < 2; h++) {
                    uint32_t kbb = kpb + (uint32_t)(h * 32);
                    uint32_t Aa[2][4];
#pragma unroll
                    for (int mt = 0; mt < 2; mt++)
                        ldsm4(Aa[mt][0], Aa[mt][1], Aa[mt][2], Aa[mt][3], stA + aBase[mt] + kbb);
#pragma unroll
                    for (int mt = 0; mt < 2; mt++)
#pragma unroll
                        for (int nt = 0; nt < 2; nt++) {
                            mma16816(acc0[mt][nt], Aa[mt][0], Aa[mt][1], Aa[mt][2], Aa[mt][3],
                                     Bq0[nt][h * 2], Bq0[nt][h * 2 + 1]);
                            mma16816(accWi[mt][nt], Aa[mt][0], Aa[mt][1], Aa[mt][2], Aa[mt][3],
                                     BqW[nt][h * 2], BqW[nt][h * 2 + 1]);
                        }
                }
            }
        }

        // layer0 partials -> zs
        {
            float* zb = zs + wk * ZBANK;
#pragma unroll
            for (int mt = 0; mt < 2; mt++)
#pragma unroll
                for (int nt = 0; nt < 2; nt++) {
                    int r0 = wm * 32 + mt * 16 + g;
                    int c0 = wn * 16 + nt * 8 + 2 * t4;
                    zb[r0 * 36 + c0]     = acc0[mt][nt][0];
                    zb[r0 * 36 + c0 + 1] = acc0[mt][nt][1];
                    zb[(r0 + 8) * 36 + c0]     = acc0[mt][nt][2];
                    zb[(r0 + 8) * 36 + c0 + 1] = acc0[mt][nt][3];
                }
        }
        __syncthreads();

        if (s >= 1) issueH(1);

        // tail0
        if (s < T_) {
#pragma unroll
            for (int it = 0; it < 2; it++) {
                int b = it ? bb2 : bb;
                float keep = 1.0f - rst0[it];
                int zi_i = b * 36 + 4 * jl;
                float zi = gp[it].x + keep * (zs[zi_i + 0] + zs[ZBANK + zi_i + 0]);
                float zf = gp[it].y + keep * (zs[zi_i + 1] + zs[ZBANK + zi_i + 1]);
                float zg = gp[it].z + keep * (zs[zi_i + 2] + zs[ZBANK + zi_i + 2]);
                float zo = gp[it].w + keep * (zs[zi_i + 3] + zs[ZBANK + zi_i + 3]);
                float cn = sigmoidf_(zf) * keep * c0r[it] + sigmoidf_(zi) * tanhf_(zg);
                float hn = sigmoidf_(zo) * tanhf_(cn);
                c0r[it] = cn;
                g_h0p[(s + 1) & 1][b * H_ + j] = __float2half_rn(hn);
                if (s == T_ - 1) {
                    out[OUTS_ + (b * 2 + 0) * H_ + j] = hn;
                    out[OUTS_ + 2 * B_ * H_ + (b * 2 + 0) * H_ + j] = cn;
                }
            }
        }

        float hn_s[2], cn_s[2];
        if (s >= 1) {
            float accWh[2][2][4];
#pragma unroll
            for (int a = 0; a < 2; a++)
#pragma unroll
                for (int b = 0; b < 2; b++)
#pragma unroll
                    for (int c = 0; c < 4; c++) accWh[a][b][c] = 0.f;

            for (int c = 0; c < 8; c++) {
                if (c + 1 < 8) cp_wait<1>(); else cp_wait<0>();
                __syncthreads();
                if (c + 2 < 8) issueH(c + 2);
                uint32_t stA = sA_u + (uint32_t)((c % 3) * ASTG * 2);
                uint32_t wOffC = (uint32_t)(c * 128 * 2);
#pragma unroll
                for (int kpi = 0; kpi < 2; kpi++) {
                    int kp = kpi * 2 + wk;
                    uint32_t kpb = (uint32_t)(kp * 64);
                    uint32_t Bq1[2][4];
#pragma unroll
                    for (int nt = 0; nt < 2; nt++)
                        ldsm4(Bq1[nt][0], Bq1[nt][1], Bq1[nt][2], Bq1[nt][3],
                              sW1_u + wBase[nt] + wOffC + kpb);
#pragma unroll
                    for (int h = 0; h < 2; h++) {
                        uint32_t kbb = kpb + (uint32_t)(h * 32);
                        uint32_t Aa[2][4];
#pragma unroll
                        for (int mt = 0; mt < 2; mt++)
                            ldsm4(Aa[mt][0], Aa[mt][1], Aa[mt][2], Aa[mt][3], stA + aBase[mt] + kbb);
#pragma unroll
                        for (int mt = 0; mt < 2; mt++)
#pragma unroll
                            for (int nt = 0; nt < 2; nt++)
                                mma16816(accWh[mt][nt], Aa[mt][0], Aa[mt][1], Aa[mt][2], Aa[mt][3],
                                         Bq1[nt][h * 2], Bq1[nt][h * 2 + 1]);
                    }
                }
            }

            {
                float* zb = zs + wk * ZBANK;
#pragma unroll
                for (int mt = 0; mt < 2; mt++)
#pragma unroll
                    for (int nt = 0; nt < 2; nt++) {
                        int r0 = wm * 32 + mt * 16 + g;
                        int c0 = wn * 16 + nt * 8 + 2 * t4;
                        float k0f = kw[mt * 2 + 0], k1f = kw[mt * 2 + 1];
                        zb[r0 * 36 + c0]     = k0f * accWh[mt][nt][0] + accWi[mt][nt][0];
                        zb[r0 * 36 + c0 + 1] = k0f * accWh[mt][nt][1] + accWi[mt][nt][1];
                        zb[(r0 + 8) * 36 + c0]     = k1f * accWh[mt][nt][2] + accWi[mt][nt][2];
                        zb[(r0 + 8) * 36 + c0 + 1] = k1f * accWh[mt][nt][3] + accWi[mt][nt][3];
                    }
            }
            __syncthreads();

            // tail1
#pragma unroll
            for (int it = 0; it < 2; it++) {
                int b = it ? bb2 : bb;
                float keep = 1.0f - rst1[it];
                int zi_i = b * 36 + 4 * jl;
                float zi = b1v.x + (zs[zi_i + 0] + zs[ZBANK + zi_i + 0]);
                float zf = b1v.y + (zs[zi_i + 1] + zs[ZBANK + zi_i + 1]);
                float zg = b1v.z + (zs[zi_i + 2] + zs[ZBANK + zi_i + 2]);
                float zo = b1v.w + (zs[zi_i + 3] + zs[ZBANK + zi_i + 3]);
                float cn = sigmoidf_(zf) * keep * c1r[it] + sigmoidf_(zi) * tanhf_(zg);
                float hn = sigmoidf_(zo) * tanhf_(cn);
                c1r[it] = cn; cn_s[it] = cn; hn_s[it] = hn;
                g_h1p[s & 1][b * H_ + j] = __float2half_rn(hn);
                if (s == T_) {
                    out[OUTS_ + (b * 2 + 1) * H_ + j] = hn;
                    out[OUTS_ + 2 * B_ * H_ + (b * 2 + 1) * H_ + j] = cn;
                }
            }
        }

        // barrier arrive
        __syncthreads();
        if (tid == 0) {
            __threadfence();
            unsigned grp = (unsigned)rbid >> 4;
            if (atomicAdd(&g_bar_grp[grp], 1u) == 15u) {
                g_bar_grp[grp] = 0u;
                if (atomicAdd(&g_bar_root, 1u) == 7u) {
                    g_bar_root = 0u;
                    __threadfence();
                    g_bar_gen = gen0 + s + 1;
                }
            }
        }

        // overlap: output stores + reset/kw prefetch
        if (s >= 1) {
            int t1 = s - 1;
#pragma unroll
            for (int it = 0; it < 2; it++) {
                int b = it ? bb2 : bb;
                __stcs(&out[(size_t)t1 * B_ * H_ + b * H_ + j], hn_s[it]);
            }
        }
        if (s + 1 <= T_) {
            rst1[0] = rst0[0]; rst1[1] = rst0[1];
            if (s + 1 < T_) {
                rst0[0] = (float)reset[(s + 1) * B_ + bb];
                rst0[1] = (float)reset[(s + 1) * B_ + bb2];
            }
#pragma unroll
            for (int i = 0; i < 4; i++)
                kw[i] = 1.0f - (float)reset[s * B_ + wrow[i]];
        }

        // barrier wait + G0-producer wait for next row-tile
        if (tid == 0) {
            while (ld_acq(&g_bar_gen) < gen0 + s + 1) { }
            if (s + 1 < T_) {
                unsigned by2 = (unsigned)(s + 1) >> 1;
                while (ld_acq(&g_g0_done[by2]) < 32u) { }
            }
        }
        __syncthreads();

        // gp prefetch for step s+1 (consumed a full step later)
        if (s + 1 < T_) {
            gp[0] = __ldcs((const float4*)&g_G0[((size_t)(s + 1) * B_ + bb) * G_ + n0 + 4 * jl]);
            gp[1] = __ldcs((const float4*)&g_G0[((size_t)(s + 1) * B_ + bb2) * G_ + n0 + 4 * jl]);
        }
    }
}

// ---------------- fused kernel ----------------
__global__ __launch_bounds__(256, 1) void fused_kernel(const int* __restrict__ reset,
                                                       float* __restrict__ out)
{
    extern __shared__ char smraw[];
    int bid = blockIdx.x;
    if (bid < NB_) merged_body(bid, reset, out, smraw);
    else           g0_body(bid - NB_, smraw);
}

// ---------------- launch ----------------
extern "C" void kernel_launch(void* const* d_in, const int* in_sizes, int n_in,
                              void* d_out, int out_size)
{
    (void)in_sizes; (void)n_in; (void)out_size;
    const float* input = (const float*)d_in[0];
    const int*   reset = (const int*)d_in[1];
    const float* h0    = (const float*)d_in[2];
    const float* c0    = (const float*)d_in[3];
    const float* Wi0   = (const float*)d_in[4];
    const float* Wh0   = (const float*)d_in[5];
    const float* bi0   = (const float*)d_in[6];
    const float* bh0   = (const float*)d_in[7];
    const float* Wi1   = (const float*)d_in[8];
    const float* Wh1   = (const float*)d_in[9];
    const float* bi1   = (const float*)d_in[10];
    const float* bh1   = (const float*)d_in[11];
    float* out = (float*)d_out;

    cudaFuncSetAttribute(fused_kernel, cudaFuncAttributeMaxDynamicSharedMemorySize, MERGED_SMEM);

    setup_kernel<<<2848, 256>>>(input, h0, c0, Wi0, Wh0, bi0, bh0, Wi1, Wh1, bi1, bh1);
    fused_kernel<<<NB_ + G0B_, 256, MERGED_SMEM>>>(reset, out);
}